// round 11
// baseline (speedup 1.0000x reference)
#include <cuda_runtime.h>
#include <cstdint>

#define S_LEN 2048
#define DM    1024
#define NH    16
#define HD    64
#define BATCH 2
#define M_TOT (BATCH * S_LEN)   // 4096
#define XN4   (M_TOT * DM / 4)  // 1048576
#define WN4   (DM * DM / 4)     // 262144

// ---------------- scratch (device globals: no allocation allowed) ----------
__device__ float g_Q[M_TOT * DM];
__device__ float g_K[M_TOT * DM];
__device__ float g_V[M_TOT * DM];
__device__ float g_O[M_TOT * DM];
__device__ float g_X[M_TOT * DM];          // tf32-rounded x
__device__ float g_WR[4][DM * DM];         // tf32-rounded Wq,Wk,Wv,Wo
__device__ float g_pad[BATCH * S_LEN];     // 1.0f = padded (id==0), 0.0f = valid
__device__ float g_padany[BATCH * 32];     // per-64-key-block any-pad flag

// ---------------------------------------------------------------------------
__device__ __forceinline__ uint32_t f2tf(float f) {
    uint32_t u;
    asm("cvt.rna.tf32.f32 %0, %1;" : "=r"(u) : "f"(f));
    return u;
}

__device__ __forceinline__ void mma8(float* c, const uint32_t* a, const uint32_t* b) {
    asm volatile(
        "mma.sync.aligned.m16n8k8.row.col.f32.tf32.tf32.f32 "
        "{%0,%1,%2,%3},{%4,%5,%6,%7},{%8,%9},{%0,%1,%2,%3};"
        : "+f"(c[0]), "+f"(c[1]), "+f"(c[2]), "+f"(c[3])
        : "r"(a[0]), "r"(a[1]), "r"(a[2]), "r"(a[3]), "r"(b[0]), "r"(b[1]));
}

__device__ __forceinline__ void cpa16(uint32_t dst, const float* src) {
    asm volatile("cp.async.cg.shared.global [%0], [%1], 16;" :: "r"(dst), "l"(src));
}

__device__ __forceinline__ void cpa4(uint32_t dst, const float* src) {
    asm volatile("cp.async.ca.shared.global [%0], [%1], 4;" :: "r"(dst), "l"(src));
}

// ---------------------------------------------------------------------------
// One-shot pre-pass: tf32-round x + 4 weights; LAST block computes pad flags
// (int32/int64 sniffing, see R0 notes) and per-64-block any-pad flags.
// ---------------------------------------------------------------------------
__global__ void round_all(const float4* __restrict__ x,
                          const float4* __restrict__ wq, const float4* __restrict__ wk,
                          const float4* __restrict__ wv, const float4* __restrict__ wo,
                          float4* __restrict__ X, float4* __restrict__ WR,
                          const int* __restrict__ ids)
{
    if (blockIdx.x == gridDim.x - 1) {
        // pad block
        __shared__ int orv;
        if (threadIdx.x == 0) orv = 0;
        __syncthreads();
        int local = 0;
        for (int i = threadIdx.x; i < 2048; i += blockDim.x)
            local |= ids[2 * i + 1];
        atomicOr(&orv, local);
        __syncthreads();
        bool is64 = (orv == 0);
        for (int i = threadIdx.x; i < BATCH * S_LEN; i += blockDim.x) {
            int nz = is64 ? ((ids[2 * i] | ids[2 * i + 1]) != 0) : (ids[i] != 0);
            g_pad[i] = nz ? 0.0f : 1.0f;
        }
        __syncthreads();   // g_pad visible block-wide
        if (threadIdx.x < BATCH * 32) {
            float any = 0.0f;
            for (int j = 0; j < 64; j++)
                any = fmaxf(any, g_pad[threadIdx.x * 64 + j]);
            g_padany[threadIdx.x] = any;
        }
        return;
    }

    int i = blockIdx.x * blockDim.x + threadIdx.x;
    const float4* src;
    float4* dst;
    if (i < XN4) {
        src = x + i; dst = X + i;
    } else {
        int j = i - XN4;
        int w = j >> 18;
        int r = j & (WN4 - 1);
        src = (w == 0 ? wq : w == 1 ? wk : w == 2 ? wv : wo) + r;
        dst = WR + (size_t)w * WN4 + r;
    }
    float4 v = *src;
    float4 o;
    o.x = __uint_as_float(f2tf(v.x));
    o.y = __uint_as_float(f2tf(v.y));
    o.z = __uint_as_float(f2tf(v.z));
    o.w = __uint_as_float(f2tf(v.w));
    *dst = o;
}

// ---------------------------------------------------------------------------
// TF32 tensor-core GEMM (NT), cp.async 3-stage pipeline, BK=32. (R9, passing)
// gridDim.z selects (W,bias,C) -> fused QKV in one launch.
// ---------------------------------------------------------------------------
#define GSTAGES 3
#define GSTAGE_WORDS (2 * 128 * 32)
#define GEMM_SMEM_BYTES (GSTAGES * GSTAGE_WORDS * 4)      // 96 KB

__global__ __launch_bounds__(256, 2)
void gemm_tf32(const float* __restrict__ A, const float* __restrict__ Wbase,
               const float* __restrict__ b0, const float* __restrict__ b1,
               const float* __restrict__ b2,
               float* __restrict__ C0, float* __restrict__ C1, float* __restrict__ C2,
               int roundOut)
{
    extern __shared__ uint32_t sm[];

    const int z = blockIdx.z;
    const float* W    = Wbase + (size_t)z * DM * DM;
    const float* bias = (z == 0) ? b0 : (z == 1) ? b1 : b2;
    float*       C    = (z == 0) ? C0 : (z == 1) ? C1 : C2;

    const int tid  = threadIdx.x;
    const int lane = tid & 31;
    const int wid  = tid >> 5;
    const int g    = lane >> 2;
    const int t    = lane & 3;
    const int warp_m = wid & 1;
    const int warp_n = wid >> 1;

    const int row0 = blockIdx.y * 128;
    const int col0 = blockIdx.x * 128;

    const int ldr  = tid >> 1;
    const int ldcb = (tid & 1) * 4;
    const float* Arow = A + (size_t)(row0 + ldr) * DM;
    const float* Wrow = W + (size_t)(col0 + ldr) * DM;
    uint32_t smbase = (uint32_t)__cvta_generic_to_shared((void*)sm);

    uint32_t adst[4], bdst[4];
#pragma unroll
    for (int cc = 0; cc < 4; cc++) {
        int c = ldcb + cc;
        uint32_t woff = (uint32_t)(ldr * 32 + ((c ^ (ldr & 7)) * 4));
        adst[cc] = smbase + woff * 4;
        bdst[cc] = smbase + (4096 + woff) * 4;
    }

    float c[4][4][4];
#pragma unroll
    for (int i = 0; i < 4; i++)
#pragma unroll
        for (int j = 0; j < 4; j++)
#pragma unroll
            for (int q = 0; q < 4; q++) c[i][j][q] = 0.0f;

    const int nIter = DM / 32;

#pragma unroll
    for (int s = 0; s < GSTAGES - 1; s++) {
        uint32_t soff = (uint32_t)(s * GSTAGE_WORDS * 4);
        int k0 = s * 32;
#pragma unroll
        for (int cc = 0; cc < 4; cc++) {
            int c4 = (ldcb + cc) * 4;
            cpa16(adst[cc] + soff, Arow + k0 + c4);
            cpa16(bdst[cc] + soff, Wrow + k0 + c4);
        }
        asm volatile("cp.async.commit_group;");
    }

    const int a_m0 = warp_m * 64 + g;
    const int b_n0 = warp_n * 32 + g;

    for (int it = 0; it < nIter; it++) {
        asm volatile("cp.async.wait_group 1;");
        __syncthreads();

        const uint32_t* As = sm + (it % GSTAGES) * GSTAGE_WORDS;
        const uint32_t* Bs = As + 4096;

#pragma unroll
        for (int sh = 0; sh < 4; sh++) {
            const int ch0 = ((2 * sh) ^ g) * 4 + t;
            const int ch1 = ((2 * sh + 1) ^ g) * 4 + t;
            uint32_t af[4][4];
            uint32_t bf[4][2];
#pragma unroll
            for (int i = 0; i < 4; i++) {
                int m = (a_m0 + i * 16) * 32;
                af[i][0] = As[m + ch0];
                af[i][1] = As[m + 256 + ch0];
                af[i][2] = As[m + ch1];
                af[i][3] = As[m + 256 + ch1];
            }
#pragma unroll
            for (int j = 0; j < 4; j++) {
                int n = (b_n0 + j * 8) * 32;
                bf[j][0] = Bs[n + ch0];
                bf[j][1] = Bs[n + ch1];
            }
#pragma unroll
            for (int i = 0; i < 4; i++)
#pragma unroll
                for (int j = 0; j < 4; j++)
                    mma8(c[i][j], af[i], bf[j]);
        }

        int nk = (it + GSTAGES - 1) * 32;
        if (nk < DM) {
            uint32_t soff = (uint32_t)(((it + GSTAGES - 1) % GSTAGES) * GSTAGE_WORDS * 4);
#pragma unroll
            for (int cc = 0; cc < 4; cc++) {
                int c4 = (ldcb + cc) * 4;
                cpa16(adst[cc] + soff, Arow + nk + c4);
                cpa16(bdst[cc] + soff, Wrow + nk + c4);
            }
        }
        asm volatile("cp.async.commit_group;");
    }

#pragma unroll
    for (int i = 0; i < 4; i++) {
        int rm = row0 + warp_m * 64 + i * 16 + g;
#pragma unroll
        for (int j = 0; j < 4; j++) {
            int cn = col0 + warp_n * 32 + j * 8 + 2 * t;
            float b0v = bias[cn], b1v = bias[cn + 1];
            float o00 = c[i][j][0] + b0v, o01 = c[i][j][1] + b1v;
            float o10 = c[i][j][2] + b0v, o11 = c[i][j][3] + b1v;
            if (roundOut) {
                o00 = __uint_as_float(f2tf(o00));
                o01 = __uint_as_float(f2tf(o01));
                o10 = __uint_as_float(f2tf(o10));
                o11 = __uint_as_float(f2tf(o11));
            }
            *(float2*)&C[(size_t)rm * DM + cn]       = make_float2(o00, o01);
            *(float2*)&C[(size_t)(rm + 8) * DM + cn] = make_float2(o10, o11);
        }
    }
}

// ---------------------------------------------------------------------------
// Flash attention v2, tf32 mma.sync, cp.async double-buffered K/V + pad,
// causal-paired q-tiles, K stored [key][d], clean-tile mask fast path.
// ---------------------------------------------------------------------------
#define FLD 72
#define KV_WORDS (64 * FLD)
// sP(128*FLD) + K(2*KV) + V(2*KV) + pad(128) + any(2, padded to 4)
#define FLASH_SMEM_BYTES ((128 * FLD + 4 * KV_WORDS + 132) * 4)

__global__ __launch_bounds__(256)
void flash_tc(const float* __restrict__ Q, const float* __restrict__ K,
              const float* __restrict__ V, float* __restrict__ O)
{
    extern __shared__ uint32_t smem[];
    uint32_t* sP  = smem;
    uint32_t* sKb = smem + 128 * FLD;
    uint32_t* sVb = smem + 128 * FLD + 2 * KV_WORDS;
    float*    sPad = (float*)(smem + 128 * FLD + 4 * KV_WORDS);   // 2 x 64
    float*    sAny = (float*)(smem + 128 * FLD + 4 * KV_WORDS + 128);  // 2

    const int qx  = blockIdx.x;
    const int h   = blockIdx.y;
    const int bb  = blockIdx.z;
    const int tid = threadIdx.x;
    const int lane = tid & 31;
    const int w    = tid >> 5;
    const int g    = lane >> 2;
    const int t    = lane & 3;
    const int hoff = h * HD;

    int ld_row[4], ld_c4[4];
    uint32_t kdst[4], vdst[4], pad_dst, any_dst;
    {
        uint32_t smb = (uint32_t)__cvta_generic_to_shared((void*)smem);
        uint32_t kb = smb + (128 * FLD) * 4;
        uint32_t vb = smb + (128 * FLD + 2 * KV_WORDS) * 4;
        pad_dst = smb + (128 * FLD + 4 * KV_WORDS) * 4;
        any_dst = pad_dst + 128 * 4;
#pragma unroll
        for (int it = 0; it < 4; it++) {
            int linear = it * 256 + tid;
            ld_row[it] = linear >> 4;
            ld_c4[it]  = (linear & 15) * 4;
            uint32_t off = (uint32_t)(ld_row[it] * FLD + ld_c4[it]) * 4;
            kdst[it] = kb + off;
            vdst[it] = vb + off;
        }
    }

#pragma unroll 1
    for (int sub = 0; sub < 2; sub++) {
        const int qt = (sub == 0) ? qx : (15 - qx);
        const int qlow  = qt * 128 + w * 16 + g;
        const int qhigh = qlow + 8;
        const int warp_qmin = qt * 128 + w * 16;
        const size_t qrowbase = (size_t)(bb * S_LEN + qt * 128 + w * 16);
        const int ntiles = 2 * qt + 2;

        uint32_t aQ[8][4];
#pragma unroll
        for (int kd = 0; kd < 8; kd++) {
            int cq = hoff + kd * 8 + t;
            aQ[kd][0] = __float_as_uint(Q[(qrowbase + g) * DM + cq] * 0.125f);
            aQ[kd][1] = __float_as_uint(Q[(qrowbase + g + 8) * DM + cq] * 0.125f);
            aQ[kd][2] = __float_as_uint(Q[(qrowbase + g) * DM + cq + 4] * 0.125f);
            aQ[kd][3] = __float_as_uint(Q[(qrowbase + g + 8) * DM + cq + 4] * 0.125f);
        }

        float m0 = -3.0e38f, m1 = -3.0e38f, l0 = 0.0f, l1 = 0.0f;
        float cO[8][4];
#pragma unroll
        for (int j = 0; j < 8; j++)
#pragma unroll
            for (int q = 0; q < 4; q++) cO[j][q] = 0.0f;

        __syncthreads();   // prior q-tile fully consumed before buffer reuse

        // prologue: prefetch tile 0 -> buf 0 (K, V, pad, padany all async)
        {
            const int kbase = bb * S_LEN;
#pragma unroll
            for (int it = 0; it < 4; it++) {
                cpa16(kdst[it], &K[(size_t)(kbase + ld_row[it]) * DM + hoff + ld_c4[it]]);
                cpa16(vdst[it], &V[(size_t)(kbase + ld_row[it]) * DM + hoff + ld_c4[it]]);
            }
            if (tid < 16) cpa16(pad_dst + tid * 16, g_pad + kbase + tid * 4);
            if (tid == 16) cpa4(any_dst, g_padany + bb * 32);
            asm volatile("cp.async.commit_group;");
        }

        for (int kt = 0; kt < ntiles; kt++) {
            asm volatile("cp.async.wait_group 0;");
            __syncthreads();

            if (kt + 1 < ntiles) {
                const int nb = (kt + 1) & 1;
                const int kbase = bb * S_LEN + (kt + 1) * 64;
                const uint32_t boff = (uint32_t)(nb * KV_WORDS * 4);
#pragma unroll
                for (int it = 0; it < 4; it++) {
                    cpa16(kdst[it] + boff, &K[(size_t)(kbase + ld_row[it]) * DM + hoff + ld_c4[it]]);
                    cpa16(vdst[it] + boff, &V[(size_t)(kbase + ld_row[it]) * DM + hoff + ld_c4[it]]);
                }
                if (tid < 16) cpa16(pad_dst + nb * 256 + tid * 16, g_pad + kbase + tid * 4);
                if (tid == 16) cpa4(any_dst + nb * 4, g_padany + bb * 32 + kt + 1);
            }
            asm volatile("cp.async.commit_group;");

            const int buf = kt & 1;
            const uint32_t* sK = sKb + buf * KV_WORDS;
            const uint32_t* sV = sVb + buf * KV_WORDS;
            const float*    pad = sPad + buf * 64;
            const float     anyp = sAny[buf];

            // S = (Q/8) K^T  (K read as B[n=key][k=d] from [key][d] layout)
            float cS[8][4];
#pragma unroll
            for (int jn = 0; jn < 8; jn++) {
                cS[jn][0] = cS[jn][1] = cS[jn][2] = cS[jn][3] = 0.0f;
                const uint32_t* krow = sK + (jn * 8 + g) * FLD;
#pragma unroll
                for (int kd = 0; kd < 8; kd++) {
                    uint32_t bK[2];
                    bK[0] = krow[kd * 8 + t];
                    bK[1] = krow[kd * 8 + t + 4];
                    mma8(cS[jn], aQ[kd], bK);
                }
            }

            // mask (causal + pad); clean tiles skip identity masking entirely
            float mx0 = -3.0e38f, mx1 = -3.0e38f;
            const bool warp_clean = (kt * 64 + 63 <= warp_qmin) && (anyp == 0.0f);
            if (warp_clean) {
#pragma unroll
                for (int jn = 0; jn < 8; jn++) {
                    mx0 = fmaxf(mx0, fmaxf(cS[jn][0], cS[jn][1]));
                    mx1 = fmaxf(mx1, fmaxf(cS[jn][2], cS[jn][3]));
                }
            } else {
#pragma unroll
                for (int jn = 0; jn < 8; jn++) {
                    int col = jn * 8 + 2 * t;
                    int k0g = kt * 64 + col;
                    bool p0 = (pad[col] == 0.0f);
                    bool p1 = (pad[col + 1] == 0.0f);
                    cS[jn][0] = (k0g     <= qlow  && p0) ? cS[jn][0] : -1.0e9f;
                    cS[jn][1] = (k0g + 1 <= qlow  && p1) ? cS[jn][1] : -1.0e9f;
                    cS[jn][2] = (k0g     <= qhigh && p0) ? cS[jn][2] : -1.0e9f;
                    cS[jn][3] = (k0g + 1 <= qhigh && p1) ? cS[jn][3] : -1.0e9f;
                    mx0 = fmaxf(mx0, fmaxf(cS[jn][0], cS[jn][1]));
                    mx1 = fmaxf(mx1, fmaxf(cS[jn][2], cS[jn][3]));
                }
            }
            mx0 = fmaxf(mx0, __shfl_xor_sync(0xffffffffu, mx0, 1));
            mx0 = fmaxf(mx0, __shfl_xor_sync(0xffffffffu, mx0, 2));
            mx1 = fmaxf(mx1, __shfl_xor_sync(0xffffffffu, mx1, 1));
            mx1 = fmaxf(mx1, __shfl_xor_sync(0xffffffffu, mx1, 2));

            float mn0 = fmaxf(m0, mx0), mn1 = fmaxf(m1, mx1);
            float cor0 = __expf(m0 - mn0), cor1 = __expf(m1 - mn1);

            float rs0 = 0.0f, rs1 = 0.0f;
#pragma unroll
            for (int jn = 0; jn < 8; jn++) {
                cS[jn][0] = __expf(cS[jn][0] - mn0);
                cS[jn][1] = __expf(cS[jn][1] - mn0);
                cS[jn][2] = __expf(cS[jn][2] - mn1);
                cS[jn][3] = __expf(cS[jn][3] - mn1);
                rs0 += cS[jn][0] + cS[jn][1];
                rs1 += cS[jn][2] + cS[jn][3];
                cO[jn][0] *= cor0; cO[jn][1] *= cor0;
                cO[jn][2] *= cor1; cO[jn][3] *= cor1;
            }
            rs0 += __shfl_xor_sync(0xffffffffu, rs0, 1);
            rs0 += __shfl_xor_sync(0xffffffffu, rs0, 2);
            rs1 += __shfl_xor_sync(0xffffffffu, rs1, 1);
            rs1 += __shfl_xor_sync(0xffffffffu, rs1, 2);
            l0 = l0 * cor0 + rs0;
            l1 = l1 * cor1 + rs1;
            m0 = mn0; m1 = mn1;

            // P -> per-warp region of sP (warp-private: syncwarp suffices)
            {
                int pr0 = (w * 16 + g) * FLD;
                int pr1 = (w * 16 + g + 8) * FLD;
#pragma unroll
                for (int jn = 0; jn < 8; jn++) {
                    int pc = jn * 8 + 2 * t;
                    sP[pr0 + pc]     = f2tf(cS[jn][0]);
                    sP[pr0 + pc + 1] = f2tf(cS[jn][1]);
                    sP[pr1 + pc]     = f2tf(cS[jn][2]);
                    sP[pr1 + pc + 1] = f2tf(cS[jn][3]);
                }
            }
            __syncwarp();

            // O += P V
            {
                int pr0 = (w * 16 + g) * FLD;
                int pr1 = (w * 16 + g + 8) * FLD;
#pragma unroll
                for (int kd = 0; kd < 8; kd++) {
                    uint32_t aP[4];
                    aP[0] = sP[pr0 + kd * 8 + t];
                    aP[1] = sP[pr1 + kd * 8 + t];
                    aP[2] = sP[pr0 + kd * 8 + t + 4];
                    aP[3] = sP[pr1 + kd * 8 + t + 4];
#pragma unroll
                    for (int jn = 0; jn < 8; jn++) {
                        uint32_t bV[2];
                        bV[0] = sV[(kd * 8 + t) * FLD + jn * 8 + g];
                        bV[1] = sV[(kd * 8 + t + 4) * FLD + jn * 8 + g];
                        mma8(cO[jn], aP, bV);
                    }
                }
            }
        }

        // Degenerate rows (entire causal prefix padded): uniform over ALL keys.
        if (m0 <= -9.9e8f) {
            l0 = (float)S_LEN;
#pragma unroll
            for (int jn = 0; jn < 8; jn++) {
                int d0 = hoff + jn * 8 + 2 * t;
                float s0 = 0.0f, s1 = 0.0f;
                for (int key = 0; key < S_LEN; key++) {
                    const float* vp = V + (size_t)(bb * S_LEN + key) * DM + d0;
                    s0 += vp[0]; s1 += vp[1];
                }
                cO[jn][0] = s0; cO[jn][1] = s1;
            }
        }
        if (m1 <= -9.9e8f) {
            l1 = (float)S_LEN;
#pragma unroll
            for (int jn = 0; jn < 8; jn++) {
                int d0 = hoff + jn * 8 + 2 * t;
                float s0 = 0.0f, s1 = 0.0f;
                for (int key = 0; key < S_LEN; key++) {
                    const float* vp = V + (size_t)(bb * S_LEN + key) * DM + d0;
                    s0 += vp[0]; s1 += vp[1];
                }
                cO[jn][2] = s0; cO[jn][3] = s1;
            }
        }

        // store O tf32-rounded (O-projection consumes raw bits via cp.async)
        const float il0 = 1.0f / l0, il1 = 1.0f / l1;
        const size_t or0 = (qrowbase + g) * DM + hoff;
        const size_t or1 = (qrowbase + g + 8) * DM + hoff;
#pragma unroll
        for (int jn = 0; jn < 8; jn++) {
            int dc = jn * 8 + 2 * t;
            float2 v0 = make_float2(__uint_as_float(f2tf(cO[jn][0] * il0)),
                                    __uint_as_float(f2tf(cO[jn][1] * il0)));
            float2 v1 = make_float2(__uint_as_float(f2tf(cO[jn][2] * il1)),
                                    __uint_as_float(f2tf(cO[jn][3] * il1)));
            *(float2*)&O[or0 + dc] = v0;
            *(float2*)&O[or1 + dc] = v1;
        }
    }
}

// ---------------------------------------------------------------------------
extern "C" void kernel_launch(void* const* d_in, const int* in_sizes, int n_in,
                              void* d_out, int out_size)
{
    const float* x   = (const float*)d_in[0];
    const int*   ids = (const int*)  d_in[1];
    const float* Wq  = (const float*)d_in[2];
    const float* bq  = (const float*)d_in[3];
    const float* Wk  = (const float*)d_in[4];
    const float* bk  = (const float*)d_in[5];
    const float* Wv  = (const float*)d_in[6];
    const float* bv  = (const float*)d_in[7];
    const float* Wo  = (const float*)d_in[8];
    const float* bo  = (const float*)d_in[9];
    float* out = (float*)d_out;

    float *Qp, *Kp, *Vp, *Op, *Xp, *WRp;
    cudaGetSymbolAddress((void**)&Qp, g_Q);
    cudaGetSymbolAddress((void**)&Kp, g_K);
    cudaGetSymbolAddress((void**)&Vp, g_V);
    cudaGetSymbolAddress((void**)&Op, g_O);
    cudaGetSymbolAddress((void**)&Xp, g_X);
    cudaGetSymbolAddress((void**)&WRp, g_WR);

    cudaFuncSetAttribute(flash_tc, cudaFuncAttributeMaxDynamicSharedMemorySize,
                         FLASH_SMEM_BYTES);
    cudaFuncSetAttribute(gemm_tf32, cudaFuncAttributeMaxDynamicSharedMemorySize,
                         GEMM_SMEM_BYTES);

    const int TOT4 = XN4 + 4 * WN4;
    round_all<<<TOT4 / 256 + 1, 256>>>((const float4*)x, (const float4*)Wq,
                                       (const float4*)Wk, (const float4*)Wv,
                                       (const float4*)Wo, (float4*)Xp, (float4*)WRp,
                                       ids);

    dim3 gqkv(DM / 128, M_TOT / 128, 3);   // (8, 32, 3)
    gemm_tf32<<<gqkv, 256, GEMM_SMEM_BYTES>>>(Xp, WRp, bq, bk, bv, Qp, Kp, Vp, 1);

    dim3 gf(8, NH, BATCH);                 // paired q-tiles: 256 blocks
    flash_tc<<<gf, 256, FLASH_SMEM_BYTES>>>(Qp, Kp, Vp, Op);

    dim3 go(DM / 128, M_TOT / 128, 1);
    gemm_tf32<<<go, 256, GEMM_SMEM_BYTES>>>(Op, WRp + 3 * (size_t)DM * DM,
                                            bo, bo, bo, out, out, out, 0);
}

// round 12
// speedup vs baseline: 1.0014x; 1.0014x over previous
#include <cuda_runtime.h>
#include <cstdint>

#define S_LEN 2048
#define DM    1024
#define NH    16
#define HD    64
#define BATCH 2
#define M_TOT (BATCH * S_LEN)   // 4096
#define XN4   (M_TOT * DM / 4)  // 1048576
#define WN4   (DM * DM / 4)     // 262144

// ---------------- scratch (device globals: no allocation allowed) ----------
__device__ float g_Q[M_TOT * DM];
__device__ float g_K[M_TOT * DM];
__device__ float g_V[M_TOT * DM];
__device__ float g_O[M_TOT * DM];
__device__ float g_X[M_TOT * DM];          // tf32-rounded x
__device__ float g_WR[4][DM * DM];         // tf32-rounded Wq,Wk,Wv,Wo
__device__ float g_pad[BATCH * S_LEN];     // 1.0f = padded (id==0), 0.0f = valid
__device__ float g_padany[BATCH * 32];     // per-64-key-block any-pad flag

// ---------------------------------------------------------------------------
__device__ __forceinline__ uint32_t f2tf(float f) {
    uint32_t u;
    asm("cvt.rna.tf32.f32 %0, %1;" : "=r"(u) : "f"(f));
    return u;
}

__device__ __forceinline__ void mma8(float* c, const uint32_t* a, const uint32_t* b) {
    asm volatile(
        "mma.sync.aligned.m16n8k8.row.col.f32.tf32.tf32.f32 "
        "{%0,%1,%2,%3},{%4,%5,%6,%7},{%8,%9},{%0,%1,%2,%3};"
        : "+f"(c[0]), "+f"(c[1]), "+f"(c[2]), "+f"(c[3])
        : "r"(a[0]), "r"(a[1]), "r"(a[2]), "r"(a[3]), "r"(b[0]), "r"(b[1]));
}

__device__ __forceinline__ void cpa16(uint32_t dst, const float* src) {
    asm volatile("cp.async.cg.shared.global [%0], [%1], 16;" :: "r"(dst), "l"(src));
}

__device__ __forceinline__ void cpa4(uint32_t dst, const float* src) {
    asm volatile("cp.async.ca.shared.global [%0], [%1], 4;" :: "r"(dst), "l"(src));
}

// ---------------------------------------------------------------------------
// One-shot pre-pass: tf32-round x + 4 weights; LAST block computes pad flags
// (int32/int64 sniffing, see R0 notes) and per-64-block any-pad flags.
// ---------------------------------------------------------------------------
__global__ void round_all(const float4* __restrict__ x,
                          const float4* __restrict__ wq, const float4* __restrict__ wk,
                          const float4* __restrict__ wv, const float4* __restrict__ wo,
                          float4* __restrict__ X, float4* __restrict__ WR,
                          const int* __restrict__ ids)
{
    if (blockIdx.x == gridDim.x - 1) {
        // pad block
        __shared__ int orv;
        if (threadIdx.x == 0) orv = 0;
        __syncthreads();
        int local = 0;
        for (int i = threadIdx.x; i < 2048; i += blockDim.x)
            local |= ids[2 * i + 1];
        atomicOr(&orv, local);
        __syncthreads();
        bool is64 = (orv == 0);
        for (int i = threadIdx.x; i < BATCH * S_LEN; i += blockDim.x) {
            int nz = is64 ? ((ids[2 * i] | ids[2 * i + 1]) != 0) : (ids[i] != 0);
            g_pad[i] = nz ? 0.0f : 1.0f;
        }
        __syncthreads();   // g_pad visible block-wide
        if (threadIdx.x < BATCH * 32) {
            float any = 0.0f;
            for (int j = 0; j < 64; j++)
                any = fmaxf(any, g_pad[threadIdx.x * 64 + j]);
            g_padany[threadIdx.x] = any;
        }
        return;
    }

    int i = blockIdx.x * blockDim.x + threadIdx.x;
    const float4* src;
    float4* dst;
    if (i < XN4) {
        src = x + i; dst = X + i;
    } else {
        int j = i - XN4;
        int w = j >> 18;
        int r = j & (WN4 - 1);
        src = (w == 0 ? wq : w == 1 ? wk : w == 2 ? wv : wo) + r;
        dst = WR + (size_t)w * WN4 + r;
    }
    float4 v = *src;
    float4 o;
    o.x = __uint_as_float(f2tf(v.x));
    o.y = __uint_as_float(f2tf(v.y));
    o.z = __uint_as_float(f2tf(v.z));
    o.w = __uint_as_float(f2tf(v.w));
    *dst = o;
}

// ---------------------------------------------------------------------------
// TF32 tensor-core GEMM (NT), cp.async 3-stage pipeline, BK=32. (R9, passing)
// gridDim.z selects (W,bias,C) -> fused QKV in one launch.
// ---------------------------------------------------------------------------
#define GSTAGES 3
#define GSTAGE_WORDS (2 * 128 * 32)
#define GEMM_SMEM_BYTES (GSTAGES * GSTAGE_WORDS * 4)      // 96 KB

__global__ __launch_bounds__(256, 2)
void gemm_tf32(const float* __restrict__ A, const float* __restrict__ Wbase,
               const float* __restrict__ b0, const float* __restrict__ b1,
               const float* __restrict__ b2,
               float* __restrict__ C0, float* __restrict__ C1, float* __restrict__ C2,
               int roundOut)
{
    extern __shared__ uint32_t sm[];

    const int z = blockIdx.z;
    const float* W    = Wbase + (size_t)z * DM * DM;
    const float* bias = (z == 0) ? b0 : (z == 1) ? b1 : b2;
    float*       C    = (z == 0) ? C0 : (z == 1) ? C1 : C2;

    const int tid  = threadIdx.x;
    const int lane = tid & 31;
    const int wid  = tid >> 5;
    const int g    = lane >> 2;
    const int t    = lane & 3;
    const int warp_m = wid & 1;
    const int warp_n = wid >> 1;

    const int row0 = blockIdx.y * 128;
    const int col0 = blockIdx.x * 128;

    const int ldr  = tid >> 1;
    const int ldcb = (tid & 1) * 4;
    const float* Arow = A + (size_t)(row0 + ldr) * DM;
    const float* Wrow = W + (size_t)(col0 + ldr) * DM;
    uint32_t smbase = (uint32_t)__cvta_generic_to_shared((void*)sm);

    uint32_t adst[4], bdst[4];
#pragma unroll
    for (int cc = 0; cc < 4; cc++) {
        int c = ldcb + cc;
        uint32_t woff = (uint32_t)(ldr * 32 + ((c ^ (ldr & 7)) * 4));
        adst[cc] = smbase + woff * 4;
        bdst[cc] = smbase + (4096 + woff) * 4;
    }

    float c[4][4][4];
#pragma unroll
    for (int i = 0; i < 4; i++)
#pragma unroll
        for (int j = 0; j < 4; j++)
#pragma unroll
            for (int q = 0; q < 4; q++) c[i][j][q] = 0.0f;

    const int nIter = DM / 32;

#pragma unroll
    for (int s = 0; s < GSTAGES - 1; s++) {
        uint32_t soff = (uint32_t)(s * GSTAGE_WORDS * 4);
        int k0 = s * 32;
#pragma unroll
        for (int cc = 0; cc < 4; cc++) {
            int c4 = (ldcb + cc) * 4;
            cpa16(adst[cc] + soff, Arow + k0 + c4);
            cpa16(bdst[cc] + soff, Wrow + k0 + c4);
        }
        asm volatile("cp.async.commit_group;");
    }

    const int a_m0 = warp_m * 64 + g;
    const int b_n0 = warp_n * 32 + g;

    for (int it = 0; it < nIter; it++) {
        asm volatile("cp.async.wait_group 1;");
        __syncthreads();

        const uint32_t* As = sm + (it % GSTAGES) * GSTAGE_WORDS;
        const uint32_t* Bs = As + 4096;

#pragma unroll
        for (int sh = 0; sh < 4; sh++) {
            const int ch0 = ((2 * sh) ^ g) * 4 + t;
            const int ch1 = ((2 * sh + 1) ^ g) * 4 + t;
            uint32_t af[4][4];
            uint32_t bf[4][2];
#pragma unroll
            for (int i = 0; i < 4; i++) {
                int m = (a_m0 + i * 16) * 32;
                af[i][0] = As[m + ch0];
                af[i][1] = As[m + 256 + ch0];
                af[i][2] = As[m + ch1];
                af[i][3] = As[m + 256 + ch1];
            }
#pragma unroll
            for (int j = 0; j < 4; j++) {
                int n = (b_n0 + j * 8) * 32;
                bf[j][0] = Bs[n + ch0];
                bf[j][1] = Bs[n + ch1];
            }
#pragma unroll
            for (int i = 0; i < 4; i++)
#pragma unroll
                for (int j = 0; j < 4; j++)
                    mma8(c[i][j], af[i], bf[j]);
        }

        int nk = (it + GSTAGES - 1) * 32;
        if (nk < DM) {
            uint32_t soff = (uint32_t)(((it + GSTAGES - 1) % GSTAGES) * GSTAGE_WORDS * 4);
#pragma unroll
            for (int cc = 0; cc < 4; cc++) {
                int c4 = (ldcb + cc) * 4;
                cpa16(adst[cc] + soff, Arow + nk + c4);
                cpa16(bdst[cc] + soff, Wrow + nk + c4);
            }
        }
        asm volatile("cp.async.commit_group;");
    }

#pragma unroll
    for (int i = 0; i < 4; i++) {
        int rm = row0 + warp_m * 64 + i * 16 + g;
#pragma unroll
        for (int j = 0; j < 4; j++) {
            int cn = col0 + warp_n * 32 + j * 8 + 2 * t;
            float b0v = bias[cn], b1v = bias[cn + 1];
            float o00 = c[i][j][0] + b0v, o01 = c[i][j][1] + b1v;
            float o10 = c[i][j][2] + b0v, o11 = c[i][j][3] + b1v;
            if (roundOut) {
                o00 = __uint_as_float(f2tf(o00));
                o01 = __uint_as_float(f2tf(o01));
                o10 = __uint_as_float(f2tf(o10));
                o11 = __uint_as_float(f2tf(o11));
            }
            *(float2*)&C[(size_t)rm * DM + cn]       = make_float2(o00, o01);
            *(float2*)&C[(size_t)(rm + 8) * DM + cn] = make_float2(o10, o11);
        }
    }
}

// ---------------------------------------------------------------------------
// Flash attention v2, tf32 mma.sync, cp.async double-buffered K/V + pad,
// causal-paired q-tiles, K stored [key][d], clean-tile mask fast path.
// ---------------------------------------------------------------------------
#define FLD 72
#define KV_WORDS (64 * FLD)
// sP(128*FLD) + K(2*KV) + V(2*KV) + pad(128) + any(2, padded to 4)
#define FLASH_SMEM_BYTES ((128 * FLD + 4 * KV_WORDS + 132) * 4)

__global__ __launch_bounds__(256)
void flash_tc(const float* __restrict__ Q, const float* __restrict__ K,
              const float* __restrict__ V, float* __restrict__ O)
{
    extern __shared__ uint32_t smem[];
    uint32_t* sP  = smem;
    uint32_t* sKb = smem + 128 * FLD;
    uint32_t* sVb = smem + 128 * FLD + 2 * KV_WORDS;
    float*    sPad = (float*)(smem + 128 * FLD + 4 * KV_WORDS);   // 2 x 64
    float*    sAny = (float*)(smem + 128 * FLD + 4 * KV_WORDS + 128);  // 2

    const int qx  = blockIdx.x;
    const int h   = blockIdx.y;
    const int bb  = blockIdx.z;
    const int tid = threadIdx.x;
    const int lane = tid & 31;
    const int w    = tid >> 5;
    const int g    = lane >> 2;
    const int t    = lane & 3;
    const int hoff = h * HD;

    int ld_row[4], ld_c4[4];
    uint32_t kdst[4], vdst[4], pad_dst, any_dst;
    {
        uint32_t smb = (uint32_t)__cvta_generic_to_shared((void*)smem);
        uint32_t kb = smb + (128 * FLD) * 4;
        uint32_t vb = smb + (128 * FLD + 2 * KV_WORDS) * 4;
        pad_dst = smb + (128 * FLD + 4 * KV_WORDS) * 4;
        any_dst = pad_dst + 128 * 4;
#pragma unroll
        for (int it = 0; it < 4; it++) {
            int linear = it * 256 + tid;
            ld_row[it] = linear >> 4;
            ld_c4[it]  = (linear & 15) * 4;
            uint32_t off = (uint32_t)(ld_row[it] * FLD + ld_c4[it]) * 4;
            kdst[it] = kb + off;
            vdst[it] = vb + off;
        }
    }

#pragma unroll 1
    for (int sub = 0; sub < 2; sub++) {
        const int qt = (sub == 0) ? qx : (15 - qx);
        const int qlow  = qt * 128 + w * 16 + g;
        const int qhigh = qlow + 8;
        const int warp_qmin = qt * 128 + w * 16;
        const size_t qrowbase = (size_t)(bb * S_LEN + qt * 128 + w * 16);
        const int ntiles = 2 * qt + 2;

        uint32_t aQ[8][4];
#pragma unroll
        for (int kd = 0; kd < 8; kd++) {
            int cq = hoff + kd * 8 + t;
            aQ[kd][0] = __float_as_uint(Q[(qrowbase + g) * DM + cq] * 0.125f);
            aQ[kd][1] = __float_as_uint(Q[(qrowbase + g + 8) * DM + cq] * 0.125f);
            aQ[kd][2] = __float_as_uint(Q[(qrowbase + g) * DM + cq + 4] * 0.125f);
            aQ[kd][3] = __float_as_uint(Q[(qrowbase + g + 8) * DM + cq + 4] * 0.125f);
        }

        float m0 = -3.0e38f, m1 = -3.0e38f, l0 = 0.0f, l1 = 0.0f;
        float cO[8][4];
#pragma unroll
        for (int j = 0; j < 8; j++)
#pragma unroll
            for (int q = 0; q < 4; q++) cO[j][q] = 0.0f;

        __syncthreads();   // prior q-tile fully consumed before buffer reuse

        // prologue: prefetch tile 0 -> buf 0 (K, V, pad, padany all async)
        {
            const int kbase = bb * S_LEN;
#pragma unroll
            for (int it = 0; it < 4; it++) {
                cpa16(kdst[it], &K[(size_t)(kbase + ld_row[it]) * DM + hoff + ld_c4[it]]);
                cpa16(vdst[it], &V[(size_t)(kbase + ld_row[it]) * DM + hoff + ld_c4[it]]);
            }
            if (tid < 16) cpa16(pad_dst + tid * 16, g_pad + kbase + tid * 4);
            if (tid == 16) cpa4(any_dst, g_padany + bb * 32);
            asm volatile("cp.async.commit_group;");
        }

        for (int kt = 0; kt < ntiles; kt++) {
            asm volatile("cp.async.wait_group 0;");
            __syncthreads();

            if (kt + 1 < ntiles) {
                const int nb = (kt + 1) & 1;
                const int kbase = bb * S_LEN + (kt + 1) * 64;
                const uint32_t boff = (uint32_t)(nb * KV_WORDS * 4);
#pragma unroll
                for (int it = 0; it < 4; it++) {
                    cpa16(kdst[it] + boff, &K[(size_t)(kbase + ld_row[it]) * DM + hoff + ld_c4[it]]);
                    cpa16(vdst[it] + boff, &V[(size_t)(kbase + ld_row[it]) * DM + hoff + ld_c4[it]]);
                }
                if (tid < 16) cpa16(pad_dst + nb * 256 + tid * 16, g_pad + kbase + tid * 4);
                if (tid == 16) cpa4(any_dst + nb * 4, g_padany + bb * 32 + kt + 1);
            }
            asm volatile("cp.async.commit_group;");

            const int buf = kt & 1;
            const uint32_t* sK = sKb + buf * KV_WORDS;
            const uint32_t* sV = sVb + buf * KV_WORDS;
            const float*    pad = sPad + buf * 64;
            const float     anyp = sAny[buf];

            // S = (Q/8) K^T  (K read as B[n=key][k=d] from [key][d] layout)
            float cS[8][4];
#pragma unroll
            for (int jn = 0; jn < 8; jn++) {
                cS[jn][0] = cS[jn][1] = cS[jn][2] = cS[jn][3] = 0.0f;
                const uint32_t* krow = sK + (jn * 8 + g) * FLD;
#pragma unroll
                for (int kd = 0; kd < 8; kd++) {
                    uint32_t bK[2];
                    bK[0] = krow[kd * 8 + t];
                    bK[1] = krow[kd * 8 + t + 4];
                    mma8(cS[jn], aQ[kd], bK);
                }
            }

            // mask (causal + pad); clean tiles skip identity masking entirely
            float mx0 = -3.0e38f, mx1 = -3.0e38f;
            const bool warp_clean = (kt * 64 + 63 <= warp_qmin) && (anyp == 0.0f);
            if (warp_clean) {
#pragma unroll
                for (int jn = 0; jn < 8; jn++) {
                    mx0 = fmaxf(mx0, fmaxf(cS[jn][0], cS[jn][1]));
                    mx1 = fmaxf(mx1, fmaxf(cS[jn][2], cS[jn][3]));
                }
            } else {
#pragma unroll
                for (int jn = 0; jn < 8; jn++) {
                    int col = jn * 8 + 2 * t;
                    int k0g = kt * 64 + col;
                    bool p0 = (pad[col] == 0.0f);
                    bool p1 = (pad[col + 1] == 0.0f);
                    cS[jn][0] = (k0g     <= qlow  && p0) ? cS[jn][0] : -1.0e9f;
                    cS[jn][1] = (k0g + 1 <= qlow  && p1) ? cS[jn][1] : -1.0e9f;
                    cS[jn][2] = (k0g     <= qhigh && p0) ? cS[jn][2] : -1.0e9f;
                    cS[jn][3] = (k0g + 1 <= qhigh && p1) ? cS[jn][3] : -1.0e9f;
                    mx0 = fmaxf(mx0, fmaxf(cS[jn][0], cS[jn][1]));
                    mx1 = fmaxf(mx1, fmaxf(cS[jn][2], cS[jn][3]));
                }
            }
            mx0 = fmaxf(mx0, __shfl_xor_sync(0xffffffffu, mx0, 1));
            mx0 = fmaxf(mx0, __shfl_xor_sync(0xffffffffu, mx0, 2));
            mx1 = fmaxf(mx1, __shfl_xor_sync(0xffffffffu, mx1, 1));
            mx1 = fmaxf(mx1, __shfl_xor_sync(0xffffffffu, mx1, 2));

            float mn0 = fmaxf(m0, mx0), mn1 = fmaxf(m1, mx1);
            float cor0 = __expf(m0 - mn0), cor1 = __expf(m1 - mn1);

            float rs0 = 0.0f, rs1 = 0.0f;
#pragma unroll
            for (int jn = 0; jn < 8; jn++) {
                cS[jn][0] = __expf(cS[jn][0] - mn0);
                cS[jn][1] = __expf(cS[jn][1] - mn0);
                cS[jn][2] = __expf(cS[jn][2] - mn1);
                cS[jn][3] = __expf(cS[jn][3] - mn1);
                rs0 += cS[jn][0] + cS[jn][1];
                rs1 += cS[jn][2] + cS[jn][3];
                cO[jn][0] *= cor0; cO[jn][1] *= cor0;
                cO[jn][2] *= cor1; cO[jn][3] *= cor1;
            }
            rs0 += __shfl_xor_sync(0xffffffffu, rs0, 1);
            rs0 += __shfl_xor_sync(0xffffffffu, rs0, 2);
            rs1 += __shfl_xor_sync(0xffffffffu, rs1, 1);
            rs1 += __shfl_xor_sync(0xffffffffu, rs1, 2);
            l0 = l0 * cor0 + rs0;
            l1 = l1 * cor1 + rs1;
            m0 = mn0; m1 = mn1;

            // P -> per-warp region of sP (warp-private: syncwarp suffices)
            {
                int pr0 = (w * 16 + g) * FLD;
                int pr1 = (w * 16 + g + 8) * FLD;
#pragma unroll
                for (int jn = 0; jn < 8; jn++) {
                    int pc = jn * 8 + 2 * t;
                    sP[pr0 + pc]     = f2tf(cS[jn][0]);
                    sP[pr0 + pc + 1] = f2tf(cS[jn][1]);
                    sP[pr1 + pc]     = f2tf(cS[jn][2]);
                    sP[pr1 + pc + 1] = f2tf(cS[jn][3]);
                }
            }
            __syncwarp();

            // O += P V
            {
                int pr0 = (w * 16 + g) * FLD;
                int pr1 = (w * 16 + g + 8) * FLD;
#pragma unroll
                for (int kd = 0; kd < 8; kd++) {
                    uint32_t aP[4];
                    aP[0] = sP[pr0 + kd * 8 + t];
                    aP[1] = sP[pr1 + kd * 8 + t];
                    aP[2] = sP[pr0 + kd * 8 + t + 4];
                    aP[3] = sP[pr1 + kd * 8 + t + 4];
#pragma unroll
                    for (int jn = 0; jn < 8; jn++) {
                        uint32_t bV[2];
                        bV[0] = sV[(kd * 8 + t) * FLD + jn * 8 + g];
                        bV[1] = sV[(kd * 8 + t + 4) * FLD + jn * 8 + g];
                        mma8(cO[jn], aP, bV);
                    }
                }
            }
        }

        // Degenerate rows (entire causal prefix padded): uniform over ALL keys.
        if (m0 <= -9.9e8f) {
            l0 = (float)S_LEN;
#pragma unroll
            for (int jn = 0; jn < 8; jn++) {
                int d0 = hoff + jn * 8 + 2 * t;
                float s0 = 0.0f, s1 = 0.0f;
                for (int key = 0; key < S_LEN; key++) {
                    const float* vp = V + (size_t)(bb * S_LEN + key) * DM + d0;
                    s0 += vp[0]; s1 += vp[1];
                }
                cO[jn][0] = s0; cO[jn][1] = s1;
            }
        }
        if (m1 <= -9.9e8f) {
            l1 = (float)S_LEN;
#pragma unroll
            for (int jn = 0; jn < 8; jn++) {
                int d0 = hoff + jn * 8 + 2 * t;
                float s0 = 0.0f, s1 = 0.0f;
                for (int key = 0; key < S_LEN; key++) {
                    const float* vp = V + (size_t)(bb * S_LEN + key) * DM + d0;
                    s0 += vp[0]; s1 += vp[1];
                }
                cO[jn][2] = s0; cO[jn][3] = s1;
            }
        }

        // store O tf32-rounded (O-projection consumes raw bits via cp.async)
        const float il0 = 1.0f / l0, il1 = 1.0f / l1;
        const size_t or0 = (qrowbase + g) * DM + hoff;
        const size_t or1 = (qrowbase + g + 8) * DM + hoff;
#pragma unroll
        for (int jn = 0; jn < 8; jn++) {
            int dc = jn * 8 + 2 * t;
            float2 v0 = make_float2(__uint_as_float(f2tf(cO[jn][0] * il0)),
                                    __uint_as_float(f2tf(cO[jn][1] * il0)));
            float2 v1 = make_float2(__uint_as_float(f2tf(cO[jn][2] * il1)),
                                    __uint_as_float(f2tf(cO[jn][3] * il1)));
            *(float2*)&O[or0 + dc] = v0;
            *(float2*)&O[or1 + dc] = v1;
        }
    }
}

// ---------------------------------------------------------------------------
extern "C" void kernel_launch(void* const* d_in, const int* in_sizes, int n_in,
                              void* d_out, int out_size)
{
    const float* x   = (const float*)d_in[0];
    const int*   ids = (const int*)  d_in[1];
    const float* Wq  = (const float*)d_in[2];
    const float* bq  = (const float*)d_in[3];
    const float* Wk  = (const float*)d_in[4];
    const float* bk  = (const float*)d_in[5];
    const float* Wv  = (const float*)d_in[6];
    const float* bv  = (const float*)d_in[7];
    const float* Wo  = (const float*)d_in[8];
    const float* bo  = (const float*)d_in[9];
    float* out = (float*)d_out;

    float *Qp, *Kp, *Vp, *Op, *Xp, *WRp;
    cudaGetSymbolAddress((void**)&Qp, g_Q);
    cudaGetSymbolAddress((void**)&Kp, g_K);
    cudaGetSymbolAddress((void**)&Vp, g_V);
    cudaGetSymbolAddress((void**)&Op, g_O);
    cudaGetSymbolAddress((void**)&Xp, g_X);
    cudaGetSymbolAddress((void**)&WRp, g_WR);

    cudaFuncSetAttribute(flash_tc, cudaFuncAttributeMaxDynamicSharedMemorySize,
                         FLASH_SMEM_BYTES);
    cudaFuncSetAttribute(gemm_tf32, cudaFuncAttributeMaxDynamicSharedMemorySize,
                         GEMM_SMEM_BYTES);

    const int TOT4 = XN4 + 4 * WN4;
    round_all<<<TOT4 / 256 + 1, 256>>>((const float4*)x, (const float4*)Wq,
                                       (const float4*)Wk, (const float4*)Wv,
                                       (const float4*)Wo, (float4*)Xp, (float4*)WRp,
                                       ids);

    dim3 gqkv(DM / 128, M_TOT / 128, 3);   // (8, 32, 3)
    gemm_tf32<<<gqkv, 256, GEMM_SMEM_BYTES>>>(Xp, WRp, bq, bk, bv, Qp, Kp, Vp, 1);

    dim3 gf(8, NH, BATCH);                 // paired q-tiles: 256 blocks
    flash_tc<<<gf, 256, FLASH_SMEM_BYTES>>>(Qp, Kp, Vp, Op);

    dim3 go(DM / 128, M_TOT / 128, 1);
    gemm_tf32<<<go, 256, GEMM_SMEM_BYTES>>>(Op, WRp + 3 * (size_t)DM * DM,
                                            bo, bo, bo, out, out, out, 0);
}